// round 17
// baseline (speedup 1.0000x reference)
#include <cuda_runtime.h>

// Problem constants (fixed by the dataset)
#define BATCH 8192
#define HDIM  512
#define DPTH  16
#define WPB   8                 // warps per block
#define NBLK  (BATCH / WPB)     // 1024 CTAs

// Scratch (__device__ globals per allocation rules). Zero-initialized at
// module load; the globally-last warp resets everything each launch so every
// graph replay starts clean.
__device__ float g_perword[BATCH];
__device__ unsigned int g_ctacnt[NBLK];
__device__ unsigned int g_done;

// Warp-per-sample streaming kernel (EXACT R6/R14 mainloop) + warp-ticket
// fused reduction: NO __syncthreads, NO second kernel. Per-warp release
// ticket on a per-CTA counter (1024 distinct addresses -> fast atomics),
// CTA winners take one global ticket (1024 total), globally-last WARP sums
// all 8192 losses in fixed order -> bitwise-deterministic mean.
__global__ __launch_bounds__(256) void hs_fused_kernel(
    const float* __restrict__ hidden,     // [BATCH, HDIM]
    const int*   __restrict__ target,     // [BATCH]
    const float* __restrict__ weights,    // [V, DPTH, HDIM]
    const float* __restrict__ codes,      // [V, DPTH]
    const int*   __restrict__ lengths,    // [V]
    float*       __restrict__ out)        // [1]
{
    const int warp = threadIdx.x >> 5;
    const int lane = threadIdx.x & 31;
    const int b    = blockIdx.x * WPB + warp;

    const int word = target[b];           // broadcast load

    // hidden[b]: lane takes float4 {lane, lane+32, lane+64, lane+96}
    const float4* hp = reinterpret_cast<const float4*>(hidden + (size_t)b * HDIM);
    float4 h[4];
    #pragma unroll
    for (int i = 0; i < 4; i++) h[i] = hp[lane + 32 * i];

    const float4* wp =
        reinterpret_cast<const float4*>(weights + (size_t)word * DPTH * HDIM);

    float acc[DPTH];
    #pragma unroll
    for (int d = 0; d < DPTH; d += 2) {
        float4 a[4], c[4];
        #pragma unroll
        for (int i = 0; i < 4; i++) a[i] = wp[(size_t)d * 128 + lane + 32 * i];
        #pragma unroll
        for (int i = 0; i < 4; i++) c[i] = wp[(size_t)(d + 1) * 128 + lane + 32 * i];
        float s0 = 0.0f, s1 = 0.0f;
        #pragma unroll
        for (int i = 0; i < 4; i++) {
            s0 += a[i].x * h[i].x + a[i].y * h[i].y + a[i].z * h[i].z + a[i].w * h[i].w;
            s1 += c[i].x * h[i].x + c[i].y * h[i].y + c[i].z * h[i].z + c[i].w * h[i].w;
        }
        acc[d]     = s0;
        acc[d + 1] = s1;
    }

    // ---- Transposed cross-lane reduction: lane l ends with logit d = l & 15
    #pragma unroll
    for (int i = 0; i < 16; i++)
        acc[i] += __shfl_xor_sync(0xffffffff, acc[i], 16);
    #pragma unroll
    for (int i = 0; i < 8; i++) {
        const bool hi = (lane & 8);
        float send = hi ? acc[i] : acc[i + 8];
        float o = __shfl_xor_sync(0xffffffff, send, 8);
        acc[i] = (hi ? acc[i + 8] : acc[i]) + o;
    }
    #pragma unroll
    for (int i = 0; i < 4; i++) {
        const bool hi = (lane & 4);
        float send = hi ? acc[i] : acc[i + 4];
        float o = __shfl_xor_sync(0xffffffff, send, 4);
        acc[i] = (hi ? acc[i + 4] : acc[i]) + o;
    }
    #pragma unroll
    for (int i = 0; i < 2; i++) {
        const bool hi = (lane & 2);
        float send = hi ? acc[i] : acc[i + 2];
        float o = __shfl_xor_sync(0xffffffff, send, 2);
        acc[i] = (hi ? acc[i + 2] : acc[i]) + o;
    }
    {
        const bool hi = (lane & 1);
        float send = hi ? acc[0] : acc[1];
        float o = __shfl_xor_sync(0xffffffff, send, 1);
        acc[0] = (hi ? acc[1] : acc[0]) + o;
    }

    // ---- BCE-with-logits: lane l handles path node d = l & 15 ----
    const int   d = lane & 15;
    const float x = acc[0];
    const float t = codes[(size_t)word * DPTH + d];   // 64B line, bcast halves
    const int   L = lengths[word];
    float bce = fmaxf(x, 0.0f) - x * t + log1pf(expf(-fabsf(x)));
    float v   = (d < L) ? bce : 0.0f;
    #pragma unroll
    for (int o = 8; o; o >>= 1)       // sum within each 16-lane half
        v += __shfl_xor_sync(0xffffffff, v, o);

    // ---- Warp-ticket fused reduction (no barriers) ----
    unsigned int isfin = 0;
    if (lane == 0) {
        float loss = v / (float)L;
        // Loss to L2, then acq_rel ticket on this CTA's private counter.
        asm volatile("st.global.cg.f32 [%0], %1;"
                     :: "l"(&g_perword[b]), "f"(loss) : "memory");
        unsigned int t1;
        asm volatile("atom.acq_rel.gpu.global.add.u32 %0, [%1], %2;"
                     : "=r"(t1) : "l"(&g_ctacnt[blockIdx.x]), "r"(1u) : "memory");
        if (t1 == WPB - 1) {
            // This warp completed its CTA: take the global ticket. acq_rel
            // carries all 8 warps' released losses into the global order.
            unsigned int t2;
            asm volatile("atom.acq_rel.gpu.global.add.u32 %0, [%1], %2;"
                         : "=r"(t2) : "l"(&g_done), "r"(1u) : "memory");
            isfin = (t2 == NBLK - 1);
        }
    }
    isfin = __shfl_sync(0xffffffff, isfin, 0);
    if (!isfin) return;

    // Globally-last warp: every loss is release-ordered into L2 before our
    // final acquire. Fixed-order sum of all 8192 -> deterministic mean.
    const float4* p4 = reinterpret_cast<const float4*>(g_perword);
    float acc2 = 0.0f;
    #pragma unroll
    for (int i = 0; i < (BATCH / 4) / 32; i++) {   // 64 independent LDG.128
        float4 v4;
        asm volatile("ld.global.cg.v4.f32 {%0,%1,%2,%3}, [%4];"
                     : "=f"(v4.x), "=f"(v4.y), "=f"(v4.z), "=f"(v4.w)
                     : "l"(p4 + lane + 32 * i));
        acc2 += v4.x + v4.y + v4.z + v4.w;
    }
    #pragma unroll
    for (int o = 16; o; o >>= 1)
        acc2 += __shfl_xor_sync(0xffffffff, acc2, o);
    if (lane == 0) out[0] = acc2 / (float)BATCH;

    // Reset scratch counters for the next graph replay (we are globally last;
    // kernel-boundary ordering makes these visible to the next launch).
    #pragma unroll
    for (int i = 0; i < NBLK / 32; i++)
        g_ctacnt[lane + 32 * i] = 0u;
    if (lane == 0) g_done = 0u;
}

extern "C" void kernel_launch(void* const* d_in, const int* in_sizes, int n_in,
                              void* d_out, int out_size)
{
    const float* hidden  = (const float*)d_in[0];
    const int*   target  = (const int*)  d_in[1];
    const float* weights = (const float*)d_in[2];
    const float* codes   = (const float*)d_in[3];
    const int*   lengths = (const int*)  d_in[4];
    float* out = (float*)d_out;

    hs_fused_kernel<<<NBLK, 256>>>(hidden, target, weights, codes, lengths, out);
}